// round 9
// baseline (speedup 1.0000x reference)
#include <cuda_runtime.h>
#include <math.h>

#define LQ 64
#define BQ 256
#define TQ 32
#define EQ 256
#define HQ 256
#define GQ 768      // 3*H
#define KQ 32
#define NRQ 8192    // B*K beam rows
#define NPB 8       // path blocks (32 chains each)
#define GRIDP (BQ + NPB)

typedef unsigned long long u64;

// ---------------- device scratch ----------------
__device__ float d_XG[33 * GQ];      // x-gates per tag (includes b_ih)
__device__ float d_Wt[HQ * GQ];      // W_hh^T: Wt[k*G + c] = W_hh[c*H + k]
__device__ float d_WtL[HQ * TQ];     // W_lin^T
__device__ float d_h1[HQ];
__device__ float d_trans0[TQ];
__device__ float d_Hid[(NRQ + BQ) * HQ];
__device__ float d_Sc[BQ * KQ];
__device__ int   d_Btags[BQ * KQ];
__device__ float d_PS[BQ];

// ---------------- helpers ----------------
__device__ __forceinline__ float fsig(float x)  { return 1.0f / (1.0f + __expf(-x)); }
__device__ __forceinline__ float ftanh(float x) { return 2.0f / (1.0f + __expf(-2.0f * x)) - 1.0f; }

__device__ __forceinline__ u64 pack2(float lo, float hi) {
    u64 r;
    asm("mov.b64 %0, {%1, %2};" : "=l"(r) : "f"(lo), "f"(hi));
    return r;
}
__device__ __forceinline__ void fma2(u64 &d, u64 a, u64 b) {
    asm("fma.rn.f32x2 %0, %1, %2, %0;" : "+l"(d) : "l"(a), "l"(b));
}

// ---------------- prep: XG[33][768] = W_ih @ emb[t] + b_ih ----------------
__global__ void k_prep_xg(const float* __restrict__ W_ih,
                          const float* __restrict__ emb,
                          const float* __restrict__ b_ih) {
    int o = (blockIdx.x * blockDim.x + threadIdx.x) >> 5;
    int lane = threadIdx.x & 31;
    if (o >= 33 * GQ) return;
    int t = o / GQ, c = o % GQ;
    const float* wr = W_ih + c * EQ;
    const float* er = emb + t * EQ;
    float acc = 0.f;
    for (int k = lane; k < EQ; k += 32) acc += wr[k] * er[k];
    #pragma unroll
    for (int off = 16; off; off >>= 1) acc += __shfl_down_sync(0xffffffffu, acc, off);
    if (lane == 0) d_XG[o] = acc + b_ih[c];
}

// ---------------- prep: transposes ----------------
__global__ void k_prep_tr(const float* __restrict__ W_hh,
                          const float* __restrict__ W_lin) {
    int idx = blockIdx.x * blockDim.x + threadIdx.x;
    if (idx < GQ * HQ) {
        int c = idx / HQ, k = idx % HQ;
        d_Wt[k * GQ + c] = W_hh[idx];
    } else {
        int i2 = idx - GQ * HQ;
        if (i2 < TQ * HQ) {
            int t = i2 / HQ, k = i2 % HQ;
            d_WtL[k * TQ + t] = W_lin[i2];
        }
    }
}

// ---------------- prep: h1 = gru(emb[T], 0), trans0 = lin(h1) ----------------
__global__ void k_prep_h1(const float* __restrict__ b_hh,
                          const float* __restrict__ W_lin,
                          const float* __restrict__ b_lin) {
    __shared__ float h1s[HQ];
    int j = threadIdx.x;
    float ir  = d_XG[32 * GQ + j];
    float iz  = d_XG[32 * GQ + HQ + j];
    float in_ = d_XG[32 * GQ + 2 * HQ + j];
    float r = fsig(ir + b_hh[j]);
    float z = fsig(iz + b_hh[HQ + j]);
    float n = ftanh(in_ + r * b_hh[2 * HQ + j]);
    float h = (1.f - z) * n;   // h0 == 0
    h1s[j] = h;
    d_h1[j] = h;
    __syncthreads();
    if (j < TQ) {
        float acc = b_lin[j];
        const float* wr = W_lin + j * HQ;
        for (int k = 0; k < HQ; k++) acc += wr[k] * h1s[k];
        d_trans0[j] = acc;
    }
}

// ---------------- prep: initial scores / beams / hidden / path score ----------------
__global__ void k_prep_init(const float* __restrict__ emis,
                            const int* __restrict__ tags,
                            const float* __restrict__ mask) {
    int w = threadIdx.x >> 5, lane = threadIdx.x & 31;
    int b = blockIdx.x * 8 + w;
    float m0 = mask[b];
    float v = (d_trans0[lane] + emis[b * TQ + lane]) * m0;
    int rank = 0;
    for (int j = 0; j < 32; j++) {
        float vj = __shfl_sync(0xffffffffu, v, j);
        rank += (vj > v) || (vj == v && j < lane);
    }
    d_Sc[b * KQ + rank]    = v;
    d_Btags[b * KQ + rank] = lane;
    if (lane == 0) {
        int t0 = tags[b];
        d_PS[b] = (d_trans0[t0] + emis[b * TQ + t0]) * m0;
    }
    for (int r = 0; r < KQ; r++) {
        float* dst = d_Hid + (b * KQ + r) * HQ;
        for (int c = lane; c < HQ; c += 32) dst[c] = d_h1[c];
    }
    float* dst = d_Hid + (NRQ + b) * HQ;
    for (int c = lane; c < HQ; c += 32) dst[c] = d_h1[c];
}

// ================= persistent fused stepper =================
// Block b < 256: batch b's 32 beams (GEMM + gates + lin + top-32 select + gather)
// Block >= 256:  32 path chains (GEMM + gates + lin + path-score accumulate)
// All 63 steps run inside the kernel; H lives in smem throughout.
#define SM_H2    0
#define SM_RH    32768
#define SM_ZB    65536
#define SM_CAND  98304
#define SM_STAG  102400
#define SM_SSC   102528
#define SM_SPAR  102656
#define SM_SPS   102784
#define SM_TOTAL 102912

__global__ void __launch_bounds__(256, 2)
k_persist(const float* __restrict__ emis,
          const int* __restrict__ tags,
          const float* __restrict__ mask,
          const float* __restrict__ b_hh,
          const float* __restrict__ b_lin) {
    extern __shared__ char sm[];
    float2* H2   = (float2*)(sm + SM_H2);     // [16][256] flat: row-pairs of H
    float*  RH   = (float*) (sm + SM_RH);     // r-gate, then h' [32][256]
    float*  ZB   = (float*) (sm + SM_ZB);     // z-gate [32][256]
    float*  cand = (float*) (sm + SM_CAND);   // [32][32]
    int*    stag = (int*)   (sm + SM_STAG);   // beam tag per slot / path x-tag
    float*  sSc  = (float*) (sm + SM_SSC);    // scores per slot
    int*    sPar = (int*)   (sm + SM_SPAR);   // parents
    float*  sPS  = (float*) (sm + SM_SPS);    // path scores

    int tid = threadIdx.x;
    int bid = blockIdx.x;
    bool isPath = (bid >= BQ);
    int bo = isPath ? (bid - BQ) * 32 : 0;

    // ---- load initial state ----
    if (!isPath) {
        if (tid < 32) { stag[tid] = d_Btags[bid * KQ + tid]; sSc[tid] = d_Sc[bid * KQ + tid]; }
        const float* src = d_Hid + (bid * KQ) * HQ;
        #pragma unroll
        for (int i = 0; i < 32; i++)
            ((float*)&H2[(i >> 1) * HQ + tid])[i & 1] = src[i * HQ + tid];
    } else {
        if (tid < 32) sPS[tid] = d_PS[bo + tid];
        const float* src = d_Hid + (NRQ + bo) * HQ;
        #pragma unroll
        for (int i = 0; i < 32; i++)
            ((float*)&H2[(i >> 1) * HQ + tid])[i & 1] = src[i * HQ + tid];
    }
    float bh0 = b_hh[tid], bh1 = b_hh[HQ + tid], bh2 = b_hh[2 * HQ + tid];
    float blin = b_lin[tid & 31];
    __syncthreads();

    for (int t = 1; t < LQ; t++) {
        // path blocks: stage this step's input tags into stag
        if (isPath && tid < 32) stag[tid] = tags[(t - 1) * BQ + bo + tid];
        __syncthreads();

        // ---- pass 1: gate columns r (tid) and z (tid+256) ----
        u64 aR[16], aZ[16];
        #pragma unroll
        for (int p = 0; p < 16; p++) { aR[p] = 0ull; aZ[p] = 0ull; }
        {
            const float* Wp = d_Wt + tid;
            #pragma unroll 4
            for (int k = 0; k < HQ; k++) {
                float w0 = Wp[k * GQ];
                float w1 = Wp[k * GQ + HQ];
                u64 W0 = pack2(w0, w0), W1 = pack2(w1, w1);
                #pragma unroll
                for (int p = 0; p < 16; p++) {
                    u64 h = *reinterpret_cast<const u64*>(&H2[p * HQ + k]);
                    fma2(aR[p], h, W0);
                    fma2(aZ[p], h, W1);
                }
            }
        }
        #pragma unroll
        for (int p = 0; p < 16; p++) {
            float2 gr = *(float2*)&aR[p];
            float2 gz = *(float2*)&aZ[p];
            #pragma unroll
            for (int s = 0; s < 2; s++) {
                int r = 2 * p + s;
                int xt = stag[r];
                const float* gi = d_XG + xt * GQ;
                float g0 = s ? gr.y : gr.x;
                float g1 = s ? gz.y : gz.x;
                RH[r * HQ + tid] = fsig(gi[tid] + g0 + bh0);
                ZB[r * HQ + tid] = fsig(gi[HQ + tid] + g1 + bh1);
            }
        }
        // ---- pass 2: gate column n (tid+512); combine to h' ----
        u64 aN[16];
        #pragma unroll
        for (int p = 0; p < 16; p++) aN[p] = 0ull;
        {
            const float* Wp = d_Wt + 2 * HQ + tid;
            #pragma unroll 4
            for (int k = 0; k < HQ; k++) {
                float w2 = Wp[k * GQ];
                u64 W2 = pack2(w2, w2);
                #pragma unroll
                for (int p = 0; p < 16; p++) {
                    u64 h = *reinterpret_cast<const u64*>(&H2[p * HQ + k]);
                    fma2(aN[p], h, W2);
                }
            }
        }
        #pragma unroll
        for (int p = 0; p < 16; p++) {
            float2 gn = *(float2*)&aN[p];
            float2 hpair = H2[p * HQ + tid];
            #pragma unroll
            for (int s = 0; s < 2; s++) {
                int r = 2 * p + s;
                int xt = stag[r];
                const float* gi = d_XG + xt * GQ;
                float g2 = s ? gn.y : gn.x;
                float rr = RH[r * HQ + tid];           // same-thread element
                float nn = ftanh(gi[2 * HQ + tid] + rr * (g2 + bh2));
                float ho = s ? hpair.y : hpair.x;
                float zz = ZB[r * HQ + tid];
                RH[r * HQ + tid] = nn + zz * (ho - nn);  // h'
            }
        }
        __syncthreads();

        // ---- TR = h' @ W_lin^T + b_lin; warp w -> rows 4w..4w+3, lane = tag ----
        int w = tid >> 5, lane = tid & 31;
        float ta0 = blin, ta1 = blin, ta2 = blin, ta3 = blin;
        {
            const float* hr = RH + (4 * w) * HQ;
            const float* wl = d_WtL + lane;
            #pragma unroll 4
            for (int k = 0; k < HQ; k++) {
                float v = wl[k * TQ];
                ta0 += hr[k] * v;
                ta1 += hr[HQ + k] * v;
                ta2 += hr[2 * HQ + k] * v;
                ta3 += hr[3 * HQ + k] * v;
            }
        }
        if (!isPath) {
            float em = emis[(t * BQ + bid) * TQ + lane];
            float m  = mask[t * BQ + bid];
            float ta[4] = {ta0, ta1, ta2, ta3};
            #pragma unroll
            for (int q = 0; q < 4; q++) {
                int r = 4 * w + q;
                float base = sSc[stag[r]];   // quirk: gather prior scores by beam TAG id
                cand[r * TQ + lane] = base + (ta[q] + em) * m;
            }
        } else {
            float ta[4] = {ta0, ta1, ta2, ta3};
            #pragma unroll
            for (int q = 0; q < 4; q++) {
                int r = 4 * w + q;
                int b = bo + r;
                int cur = tags[t * BQ + b];
                if (lane == cur)   // em0 quirk: emissions[0] at every step
                    sPS[r] += (ta[q] + emis[b * TQ + cur]) * mask[t * BQ + b];
            }
        }
        __syncthreads();

        // ---- top-32 select (warp 0, register-resident candidates) ----
        if (!isPath) {
            if (tid < 32) {
                float c[32];
                #pragma unroll
                for (int j = 0; j < 32; j++) c[j] = cand[j * TQ + tid];
                for (int i = 0; i < KQ; i++) {
                    float bv = -INFINITY; int bj = 0;
                    #pragma unroll
                    for (int j = 0; j < 32; j++)
                        if (c[j] > bv) { bv = c[j]; bj = j; }   // '>' keeps smallest flat idx
                    int bi = bj * 32 + tid;
                    #pragma unroll
                    for (int off = 16; off; off >>= 1) {
                        float ov = __shfl_down_sync(0xffffffffu, bv, off);
                        int   oi = __shfl_down_sync(0xffffffffu, bi, off);
                        if (ov > bv || (ov == bv && oi < bi)) { bv = ov; bi = oi; }
                    }
                    bv = __shfl_sync(0xffffffffu, bv, 0);
                    bi = __shfl_sync(0xffffffffu, bi, 0);
                    if (tid == 0) { sSc[i] = bv; stag[i] = bi & 31; sPar[i] = bi >> 5; }
                    if ((bi & 31) == tid) c[bi >> 5] = -INFINITY;
                }
            }
            __syncthreads();
            // gather: new H = h'[parent]
            #pragma unroll
            for (int i = 0; i < 32; i++) {
                float v = RH[sPar[i] * HQ + tid];
                ((float*)&H2[(i >> 1) * HQ + tid])[i & 1] = v;
            }
        } else {
            #pragma unroll
            for (int i = 0; i < 32; i++)
                ((float*)&H2[(i >> 1) * HQ + tid])[i & 1] = RH[i * HQ + tid];
        }
        __syncthreads();
    }

    // ---- writeback final state ----
    if (!isPath) { if (tid < 32) d_Sc[bid * KQ + tid] = sSc[tid]; }
    else if (tid < 32) d_PS[bo + tid] = sPS[tid];
}

// ---------------- finalize ----------------
__global__ void k_final(float* __restrict__ out) {
    __shared__ float red[BQ];
    int b = threadIdx.x;
    float m = -INFINITY;
    for (int i = 0; i < KQ; i++) m = fmaxf(m, d_Sc[b * KQ + i]);
    float s = 0.f;
    for (int i = 0; i < KQ; i++) s += expf(d_Sc[b * KQ + i] - m);
    float lse = m + logf(s);
    red[b] = d_PS[b] - lse;
    __syncthreads();
    for (int off = 128; off; off >>= 1) {
        if (b < off) red[b] += red[b + off];
        __syncthreads();
    }
    if (b == 0) out[0] = red[0];
}

// ---------------- launch ----------------
extern "C" void kernel_launch(void* const* d_in, const int* in_sizes, int n_in,
                              void* d_out, int out_size) {
    const float* emissions = (const float*)d_in[0];
    const int*   tags      = (const int*)  d_in[1];
    const float* mask      = (const float*)d_in[2];
    const float* embedding = (const float*)d_in[3];
    const float* W_ih      = (const float*)d_in[4];
    const float* W_hh      = (const float*)d_in[5];
    const float* b_ih      = (const float*)d_in[6];
    const float* b_hh      = (const float*)d_in[7];
    const float* W_lin     = (const float*)d_in[8];
    const float* b_lin     = (const float*)d_in[9];
    float* out = (float*)d_out;

    cudaFuncSetAttribute(k_persist, cudaFuncAttributeMaxDynamicSharedMemorySize, SM_TOTAL);

    k_prep_xg<<<(33 * GQ * 32 + 255) / 256, 256>>>(W_ih, embedding, b_ih);
    k_prep_tr<<<(GQ * HQ + TQ * HQ + 255) / 256, 256>>>(W_hh, W_lin);
    k_prep_h1<<<1, 256>>>(b_hh, W_lin, b_lin);
    k_prep_init<<<BQ / 8, 256>>>(emissions, tags, mask);

    k_persist<<<GRIDP, 256, SM_TOTAL>>>(emissions, tags, mask, b_hh, b_lin);

    k_final<<<1, 256>>>(out);
}

// round 10
// speedup vs baseline: 1.0028x; 1.0028x over previous
#include <cuda_runtime.h>
#include <math.h>

#define LQ 64
#define BQ 256
#define TQ 32
#define EQ 256
#define HQ 256
#define GQ 768      // 3*H
#define KQ 32
#define NRQ 8192    // B*K beam rows
#define NPB 8       // path blocks (32 chains each)
#define GRIDP (BQ + NPB)

typedef unsigned long long u64;

// ---------------- device scratch ----------------
__device__ float d_XG[33 * GQ];      // x-gates per tag (includes b_ih)
__device__ float d_Wt[HQ * GQ];      // W_hh^T: Wt[k*G + c] = W_hh[c*H + k]
__device__ float d_WtL[HQ * TQ];     // W_lin^T
__device__ float d_h1[HQ];
__device__ float d_trans0[TQ];
__device__ float d_Hid[(NRQ + BQ) * HQ];
__device__ float d_Sc[BQ * KQ];
__device__ int   d_Btags[BQ * KQ];
__device__ float d_PS[BQ];

// ---------------- helpers ----------------
__device__ __forceinline__ float fsig(float x)  { return 1.0f / (1.0f + __expf(-x)); }
__device__ __forceinline__ float ftanh(float x) { return 2.0f / (1.0f + __expf(-2.0f * x)) - 1.0f; }

__device__ __forceinline__ u64 pack2(float lo, float hi) {
    u64 r;
    asm("mov.b64 %0, {%1, %2};" : "=l"(r) : "f"(lo), "f"(hi));
    return r;
}
__device__ __forceinline__ void fma2(u64 &d, u64 a, u64 b) {
    asm("fma.rn.f32x2 %0, %1, %2, %0;" : "+l"(d) : "l"(a), "l"(b));
}

// ---------------- prep: XG[33][768] = W_ih @ emb[t] + b_ih ----------------
__global__ void k_prep_xg(const float* __restrict__ W_ih,
                          const float* __restrict__ emb,
                          const float* __restrict__ b_ih) {
    int o = (blockIdx.x * blockDim.x + threadIdx.x) >> 5;
    int lane = threadIdx.x & 31;
    if (o >= 33 * GQ) return;
    int t = o / GQ, c = o % GQ;
    const float* wr = W_ih + c * EQ;
    const float* er = emb + t * EQ;
    float acc = 0.f;
    for (int k = lane; k < EQ; k += 32) acc += wr[k] * er[k];
    #pragma unroll
    for (int off = 16; off; off >>= 1) acc += __shfl_down_sync(0xffffffffu, acc, off);
    if (lane == 0) d_XG[o] = acc + b_ih[c];
}

// ---------------- prep: transposes ----------------
__global__ void k_prep_tr(const float* __restrict__ W_hh,
                          const float* __restrict__ W_lin) {
    int idx = blockIdx.x * blockDim.x + threadIdx.x;
    if (idx < GQ * HQ) {
        int c = idx / HQ, k = idx % HQ;
        d_Wt[k * GQ + c] = W_hh[idx];
    } else {
        int i2 = idx - GQ * HQ;
        if (i2 < TQ * HQ) {
            int t = i2 / HQ, k = i2 % HQ;
            d_WtL[k * TQ + t] = W_lin[i2];
        }
    }
}

// ---------------- prep: h1 = gru(emb[T], 0), trans0 = lin(h1) ----------------
__global__ void k_prep_h1(const float* __restrict__ b_hh,
                          const float* __restrict__ W_lin,
                          const float* __restrict__ b_lin) {
    __shared__ float h1s[HQ];
    int j = threadIdx.x;
    float ir  = d_XG[32 * GQ + j];
    float iz  = d_XG[32 * GQ + HQ + j];
    float in_ = d_XG[32 * GQ + 2 * HQ + j];
    float r = fsig(ir + b_hh[j]);
    float z = fsig(iz + b_hh[HQ + j]);
    float n = ftanh(in_ + r * b_hh[2 * HQ + j]);
    float h = (1.f - z) * n;   // h0 == 0
    h1s[j] = h;
    d_h1[j] = h;
    __syncthreads();
    if (j < TQ) {
        float acc = b_lin[j];
        const float* wr = W_lin + j * HQ;
        for (int k = 0; k < HQ; k++) acc += wr[k] * h1s[k];
        d_trans0[j] = acc;
    }
}

// ---------------- prep: initial scores / beams / hidden / path score ----------------
__global__ void k_prep_init(const float* __restrict__ emis,
                            const int* __restrict__ tags,
                            const float* __restrict__ mask) {
    int w = threadIdx.x >> 5, lane = threadIdx.x & 31;
    int b = blockIdx.x * 8 + w;
    float m0 = mask[b];
    float v = (d_trans0[lane] + emis[b * TQ + lane]) * m0;
    int rank = 0;
    for (int j = 0; j < 32; j++) {
        float vj = __shfl_sync(0xffffffffu, v, j);
        rank += (vj > v) || (vj == v && j < lane);
    }
    d_Sc[b * KQ + rank]    = v;
    d_Btags[b * KQ + rank] = lane;
    if (lane == 0) {
        int t0 = tags[b];
        d_PS[b] = (d_trans0[t0] + emis[b * TQ + t0]) * m0;
    }
    for (int r = 0; r < KQ; r++) {
        float* dst = d_Hid + (b * KQ + r) * HQ;
        for (int c = lane; c < HQ; c += 32) dst[c] = d_h1[c];
    }
    float* dst = d_Hid + (NRQ + b) * HQ;
    for (int c = lane; c < HQ; c += 32) dst[c] = d_h1[c];
}

// ================= persistent fused stepper =================
// Block b < 256: batch b's 32 beams (GEMM + gates + lin + top-32 select + gather)
// Block >= 256:  32 path chains (GEMM + gates + lin + path-score accumulate)
// All 63 steps run inside the kernel; H lives in smem throughout.
#define SM_H2    0
#define SM_RH    32768
#define SM_ZB    65536
#define SM_CAND  98304
#define SM_STAG  102400
#define SM_SSC   102528
#define SM_SPAR  102656
#define SM_SPS   102784
#define SM_TOTAL 102912

__global__ void __launch_bounds__(256, 2)
k_persist(const float* __restrict__ emis,
          const int* __restrict__ tags,
          const float* __restrict__ mask,
          const float* __restrict__ b_hh,
          const float* __restrict__ b_lin) {
    extern __shared__ char sm[];
    float2* H2   = (float2*)(sm + SM_H2);     // [16][256] flat: row-pairs of H
    float*  RH   = (float*) (sm + SM_RH);     // r-gate, then h' [32][256]
    float*  ZB   = (float*) (sm + SM_ZB);     // z-gate [32][256]
    float*  cand = (float*) (sm + SM_CAND);   // [32][32]
    int*    stag = (int*)   (sm + SM_STAG);   // beam tag per slot / path x-tag
    float*  sSc  = (float*) (sm + SM_SSC);    // scores per slot
    int*    sPar = (int*)   (sm + SM_SPAR);   // parents
    float*  sPS  = (float*) (sm + SM_SPS);    // path scores

    int tid = threadIdx.x;
    int bid = blockIdx.x;
    bool isPath = (bid >= BQ);
    int bo = isPath ? (bid - BQ) * 32 : 0;

    // ---- load initial state ----
    if (!isPath) {
        if (tid < 32) { stag[tid] = d_Btags[bid * KQ + tid]; sSc[tid] = d_Sc[bid * KQ + tid]; }
        const float* src = d_Hid + (bid * KQ) * HQ;
        #pragma unroll
        for (int i = 0; i < 32; i++)
            ((float*)&H2[(i >> 1) * HQ + tid])[i & 1] = src[i * HQ + tid];
    } else {
        if (tid < 32) sPS[tid] = d_PS[bo + tid];
        const float* src = d_Hid + (NRQ + bo) * HQ;
        #pragma unroll
        for (int i = 0; i < 32; i++)
            ((float*)&H2[(i >> 1) * HQ + tid])[i & 1] = src[i * HQ + tid];
    }
    float bh0 = b_hh[tid], bh1 = b_hh[HQ + tid], bh2 = b_hh[2 * HQ + tid];
    float blin = b_lin[tid & 31];
    __syncthreads();

    for (int t = 1; t < LQ; t++) {
        // path blocks: stage this step's input tags into stag
        if (isPath && tid < 32) stag[tid] = tags[(t - 1) * BQ + bo + tid];
        __syncthreads();

        // ---- pass 1: gate columns r (tid) and z (tid+256) ----
        u64 aR[16], aZ[16];
        #pragma unroll
        for (int p = 0; p < 16; p++) { aR[p] = 0ull; aZ[p] = 0ull; }
        {
            const float* Wp = d_Wt + tid;
            #pragma unroll 4
            for (int k = 0; k < HQ; k++) {
                float w0 = Wp[k * GQ];
                float w1 = Wp[k * GQ + HQ];
                u64 W0 = pack2(w0, w0), W1 = pack2(w1, w1);
                #pragma unroll
                for (int p = 0; p < 16; p++) {
                    u64 h = *reinterpret_cast<const u64*>(&H2[p * HQ + k]);
                    fma2(aR[p], h, W0);
                    fma2(aZ[p], h, W1);
                }
            }
        }
        #pragma unroll
        for (int p = 0; p < 16; p++) {
            float2 gr = *(float2*)&aR[p];
            float2 gz = *(float2*)&aZ[p];
            #pragma unroll
            for (int s = 0; s < 2; s++) {
                int r = 2 * p + s;
                int xt = stag[r];
                const float* gi = d_XG + xt * GQ;
                float g0 = s ? gr.y : gr.x;
                float g1 = s ? gz.y : gz.x;
                RH[r * HQ + tid] = fsig(gi[tid] + g0 + bh0);
                ZB[r * HQ + tid] = fsig(gi[HQ + tid] + g1 + bh1);
            }
        }
        // ---- pass 2: gate column n (tid+512); combine to h' ----
        u64 aN[16];
        #pragma unroll
        for (int p = 0; p < 16; p++) aN[p] = 0ull;
        {
            const float* Wp = d_Wt + 2 * HQ + tid;
            #pragma unroll 4
            for (int k = 0; k < HQ; k++) {
                float w2 = Wp[k * GQ];
                u64 W2 = pack2(w2, w2);
                #pragma unroll
                for (int p = 0; p < 16; p++) {
                    u64 h = *reinterpret_cast<const u64*>(&H2[p * HQ + k]);
                    fma2(aN[p], h, W2);
                }
            }
        }
        #pragma unroll
        for (int p = 0; p < 16; p++) {
            float2 gn = *(float2*)&aN[p];
            float2 hpair = H2[p * HQ + tid];
            #pragma unroll
            for (int s = 0; s < 2; s++) {
                int r = 2 * p + s;
                int xt = stag[r];
                const float* gi = d_XG + xt * GQ;
                float g2 = s ? gn.y : gn.x;
                float rr = RH[r * HQ + tid];           // same-thread element
                float nn = ftanh(gi[2 * HQ + tid] + rr * (g2 + bh2));
                float ho = s ? hpair.y : hpair.x;
                float zz = ZB[r * HQ + tid];
                RH[r * HQ + tid] = nn + zz * (ho - nn);  // h'
            }
        }
        __syncthreads();

        // ---- TR = h' @ W_lin^T + b_lin; warp w -> rows 4w..4w+3, lane = tag ----
        int w = tid >> 5, lane = tid & 31;
        float ta0 = blin, ta1 = blin, ta2 = blin, ta3 = blin;
        {
            const float* hr = RH + (4 * w) * HQ;
            const float* wl = d_WtL + lane;
            #pragma unroll 4
            for (int k = 0; k < HQ; k++) {
                float v = wl[k * TQ];
                ta0 += hr[k] * v;
                ta1 += hr[HQ + k] * v;
                ta2 += hr[2 * HQ + k] * v;
                ta3 += hr[3 * HQ + k] * v;
            }
        }
        if (!isPath) {
            float em = emis[(t * BQ + bid) * TQ + lane];
            float m  = mask[t * BQ + bid];
            float ta[4] = {ta0, ta1, ta2, ta3};
            #pragma unroll
            for (int q = 0; q < 4; q++) {
                int r = 4 * w + q;
                float base = sSc[stag[r]];   // quirk: gather prior scores by beam TAG id
                cand[r * TQ + lane] = base + (ta[q] + em) * m;
            }
        } else {
            float ta[4] = {ta0, ta1, ta2, ta3};
            #pragma unroll
            for (int q = 0; q < 4; q++) {
                int r = 4 * w + q;
                int b = bo + r;
                int cur = tags[t * BQ + b];
                if (lane == cur)   // em0 quirk: emissions[0] at every step
                    sPS[r] += (ta[q] + emis[b * TQ + cur]) * mask[t * BQ + b];
            }
        }
        __syncthreads();

        // ---- top-32 select (warp 0, register-resident candidates) ----
        if (!isPath) {
            if (tid < 32) {
                float c[32];
                #pragma unroll
                for (int j = 0; j < 32; j++) c[j] = cand[j * TQ + tid];
                for (int i = 0; i < KQ; i++) {
                    float bv = -INFINITY; int bj = 0;
                    #pragma unroll
                    for (int j = 0; j < 32; j++)
                        if (c[j] > bv) { bv = c[j]; bj = j; }   // '>' keeps smallest flat idx
                    int bi = bj * 32 + tid;
                    #pragma unroll
                    for (int off = 16; off; off >>= 1) {
                        float ov = __shfl_down_sync(0xffffffffu, bv, off);
                        int   oi = __shfl_down_sync(0xffffffffu, bi, off);
                        if (ov > bv || (ov == bv && oi < bi)) { bv = ov; bi = oi; }
                    }
                    bv = __shfl_sync(0xffffffffu, bv, 0);
                    bi = __shfl_sync(0xffffffffu, bi, 0);
                    if (tid == 0) { sSc[i] = bv; stag[i] = bi & 31; sPar[i] = bi >> 5; }
                    if ((bi & 31) == tid) c[bi >> 5] = -INFINITY;
                }
            }
            __syncthreads();
            // gather: new H = h'[parent]
            #pragma unroll
            for (int i = 0; i < 32; i++) {
                float v = RH[sPar[i] * HQ + tid];
                ((float*)&H2[(i >> 1) * HQ + tid])[i & 1] = v;
            }
        } else {
            #pragma unroll
            for (int i = 0; i < 32; i++)
                ((float*)&H2[(i >> 1) * HQ + tid])[i & 1] = RH[i * HQ + tid];
        }
        __syncthreads();
    }

    // ---- writeback final state ----
    if (!isPath) { if (tid < 32) d_Sc[bid * KQ + tid] = sSc[tid]; }
    else if (tid < 32) d_PS[bo + tid] = sPS[tid];
}

// ---------------- finalize ----------------
__global__ void k_final(float* __restrict__ out) {
    __shared__ float red[BQ];
    int b = threadIdx.x;
    float m = -INFINITY;
    for (int i = 0; i < KQ; i++) m = fmaxf(m, d_Sc[b * KQ + i]);
    float s = 0.f;
    for (int i = 0; i < KQ; i++) s += expf(d_Sc[b * KQ + i] - m);
    float lse = m + logf(s);
    red[b] = d_PS[b] - lse;
    __syncthreads();
    for (int off = 128; off; off >>= 1) {
        if (b < off) red[b] += red[b + off];
        __syncthreads();
    }
    if (b == 0) out[0] = red[0];
}

// ---------------- launch ----------------
extern "C" void kernel_launch(void* const* d_in, const int* in_sizes, int n_in,
                              void* d_out, int out_size) {
    const float* emissions = (const float*)d_in[0];
    const int*   tags      = (const int*)  d_in[1];
    const float* mask      = (const float*)d_in[2];
    const float* embedding = (const float*)d_in[3];
    const float* W_ih      = (const float*)d_in[4];
    const float* W_hh      = (const float*)d_in[5];
    const float* b_ih      = (const float*)d_in[6];
    const float* b_hh      = (const float*)d_in[7];
    const float* W_lin     = (const float*)d_in[8];
    const float* b_lin     = (const float*)d_in[9];
    float* out = (float*)d_out;

    cudaFuncSetAttribute(k_persist, cudaFuncAttributeMaxDynamicSharedMemorySize, SM_TOTAL);

    k_prep_xg<<<(33 * GQ * 32 + 255) / 256, 256>>>(W_ih, embedding, b_ih);
    k_prep_tr<<<(GQ * HQ + TQ * HQ + 255) / 256, 256>>>(W_hh, W_lin);
    k_prep_h1<<<1, 256>>>(b_hh, W_lin, b_lin);
    k_prep_init<<<BQ / 8, 256>>>(emissions, tags, mask);

    k_persist<<<GRIDP, 256, SM_TOTAL>>>(emissions, tags, mask, b_hh, b_lin);

    k_final<<<1, 256>>>(out);
}

// round 11
// speedup vs baseline: 1.9260x; 1.9206x over previous
#include <cuda_runtime.h>
#include <cuda_bf16.h>
#include <math.h>

#define LQ 64
#define BQ 256
#define TQ 32
#define EQ 256
#define HQ 256
#define GQ 768
#define KQ 32
#define NRQ 8192
#define PITCH 264          // bf16 elems per smem row (528B, conflict-free ldmatrix)
#define GRIDP 132          // 128 beam CTAs (2 batches each) + 4 path CTAs (64 chains each)

typedef unsigned int u32;

// ---------------- device scratch ----------------
__device__ float d_XG[33 * GQ];          // x-gates per tag; b_ih always; +b_hh for r,z parts
__device__ float d_h1[HQ];
__device__ float d_trans0[TQ];
__device__ float d_Hid[(NRQ + BQ) * HQ];
__device__ float d_Sc[BQ * KQ];
__device__ int   d_Btags[BQ * KQ];
__device__ float d_PS[BQ];
__device__ u32   d_WB[2 * 96 * 16 * 64];   // gate B fragments: [hi/lo][ntile 96][ktile 16][lane*2+reg]
__device__ u32   d_WLB[2 * 4 * 16 * 64];   // TR  B fragments: [hi/lo][ntile 4][ktile 16][lane*2+reg]

// ---------------- helpers ----------------
__device__ __forceinline__ float fsig(float x)  { return 1.0f / (1.0f + __expf(-x)); }
__device__ __forceinline__ float ftanh(float x) { return 2.0f / (1.0f + __expf(-2.0f * x)) - 1.0f; }

__device__ __forceinline__ u32 s2u(const void* p) { return (u32)__cvta_generic_to_shared(p); }

__device__ __forceinline__ void ldmx4(u32* r, u32 addr) {
    asm volatile("ldmatrix.sync.aligned.m8n8.x4.shared.b16 {%0,%1,%2,%3}, [%4];"
                 : "=r"(r[0]), "=r"(r[1]), "=r"(r[2]), "=r"(r[3]) : "r"(addr));
}
__device__ __forceinline__ void mma16816(float* d, const u32* a, uint2 b) {
    asm volatile("mma.sync.aligned.m16n8k16.row.col.f32.bf16.bf16.f32 "
                 "{%0,%1,%2,%3}, {%4,%5,%6,%7}, {%8,%9}, {%0,%1,%2,%3};"
                 : "+f"(d[0]), "+f"(d[1]), "+f"(d[2]), "+f"(d[3])
                 : "r"(a[0]), "r"(a[1]), "r"(a[2]), "r"(a[3]), "r"(b.x), "r"(b.y));
}
__device__ __forceinline__ u32 packbf(float a, float b) {
    __nv_bfloat162 p;
    p.x = __float2bfloat16(a);
    p.y = __float2bfloat16(b);
    return *reinterpret_cast<u32*>(&p);
}

// ---------------- prep: XG[33][768] = W_ih @ emb[t] + b_ih (+ b_hh for r,z cols) ----------------
__global__ void k_prep_xg(const float* __restrict__ W_ih,
                          const float* __restrict__ emb,
                          const float* __restrict__ b_ih,
                          const float* __restrict__ b_hh) {
    int o = (blockIdx.x * blockDim.x + threadIdx.x) >> 5;
    int lane = threadIdx.x & 31;
    if (o >= 33 * GQ) return;
    int t = o / GQ, c = o % GQ;
    const float* wr = W_ih + c * EQ;
    const float* er = emb + t * EQ;
    float acc = 0.f;
    for (int k = lane; k < EQ; k += 32) acc += wr[k] * er[k];
    #pragma unroll
    for (int off = 16; off; off >>= 1) acc += __shfl_down_sync(0xffffffffu, acc, off);
    if (lane == 0) {
        float v = acc + b_ih[c];
        if (c < 2 * HQ) v += b_hh[c];   // fold b_hh into r and z parts
        d_XG[o] = v;
    }
}

// ---------------- prep: B fragment tables (bf16 hi/lo, exact mma lane order) ----------------
__global__ void k_prep_wb(const float* __restrict__ W_hh,
                          const float* __restrict__ W_lin) {
    int idx = blockIdx.x * blockDim.x + threadIdx.x;
    const int NG = 2 * 96 * 16 * 64;
    if (idx < NG) {
        int e = idx;
        int reg = e & 1;  e >>= 1;
        int lane = e & 31; e >>= 5;
        int kt = e & 15;  e >>= 4;
        int nt = e % 96;
        int wt = e / 96;
        int k0 = kt * 16 + 2 * (lane & 3) + reg * 8;
        int n  = nt * 8 + (lane >> 2);
        float w0 = W_hh[n * HQ + k0], w1 = W_hh[n * HQ + k0 + 1];
        if (wt == 0) d_WB[idx] = packbf(w0, w1);
        else {
            float h0 = __bfloat162float(__float2bfloat16(w0));
            float h1 = __bfloat162float(__float2bfloat16(w1));
            d_WB[idx] = packbf(w0 - h0, w1 - h1);
        }
    } else if (idx < NG + 2 * 4 * 16 * 64) {
        int e = idx - NG;
        int i2 = e;
        int reg = e & 1;  e >>= 1;
        int lane = e & 31; e >>= 5;
        int kt = e & 15;  e >>= 4;
        int nt = e % 4;
        int wt = e / 4;
        int k0 = kt * 16 + 2 * (lane & 3) + reg * 8;
        int n  = nt * 8 + (lane >> 2);
        float w0 = W_lin[n * HQ + k0], w1 = W_lin[n * HQ + k0 + 1];
        if (wt == 0) d_WLB[i2] = packbf(w0, w1);
        else {
            float h0 = __bfloat162float(__float2bfloat16(w0));
            float h1 = __bfloat162float(__float2bfloat16(w1));
            d_WLB[i2] = packbf(w0 - h0, w1 - h1);
        }
    }
}

// ---------------- prep: h1 = gru(emb[T], 0), trans0 = lin(h1) ----------------
__global__ void k_prep_h1(const float* __restrict__ b_hh,
                          const float* __restrict__ W_lin,
                          const float* __restrict__ b_lin) {
    __shared__ float h1s[HQ];
    int j = threadIdx.x;
    float r = fsig(d_XG[32 * GQ + j]);                 // b_hh folded
    float z = fsig(d_XG[32 * GQ + HQ + j]);
    float n = ftanh(d_XG[32 * GQ + 2 * HQ + j] + r * b_hh[2 * HQ + j]);
    float h = (1.f - z) * n;   // h0 == 0
    h1s[j] = h;
    d_h1[j] = h;
    __syncthreads();
    if (j < TQ) {
        float acc = b_lin[j];
        const float* wr = W_lin + j * HQ;
        for (int k = 0; k < HQ; k++) acc += wr[k] * h1s[k];
        d_trans0[j] = acc;
    }
}

// ---------------- prep: initial scores / beams / hidden / path score ----------------
__global__ void k_prep_init(const float* __restrict__ emis,
                            const int* __restrict__ tags,
                            const float* __restrict__ mask) {
    int w = threadIdx.x >> 5, lane = threadIdx.x & 31;
    int b = blockIdx.x * 8 + w;
    float m0 = mask[b];
    float v = (d_trans0[lane] + emis[b * TQ + lane]) * m0;
    int rank = 0;
    for (int j = 0; j < 32; j++) {
        float vj = __shfl_sync(0xffffffffu, v, j);
        rank += (vj > v) || (vj == v && j < lane);
    }
    d_Sc[b * KQ + rank]    = v;
    d_Btags[b * KQ + rank] = lane;
    if (lane == 0) {
        int t0 = tags[b];
        d_PS[b] = (d_trans0[t0] + emis[b * TQ + t0]) * m0;
    }
    for (int r = 0; r < KQ; r++) {
        float* dst = d_Hid + (b * KQ + r) * HQ;
        for (int c = lane; c < HQ; c += 32) dst[c] = d_h1[c];
    }
    float* dst = d_Hid + (NRQ + b) * HQ;
    for (int c = lane; c < HQ; c += 32) dst[c] = d_h1[c];
}

// ================= persistent fused stepper (tensor-core) =================
// smem: Hhi|Hlo|HPhi|HPlo (bf16, pitch 264) + cand + small state
#define SMB   (64 * PITCH * 2)        // 33792 bytes per bf16 buffer
#define SM_CAND  (4 * SMB)            // 135168
#define SM_STAG  (SM_CAND + 8192)     // 143360
#define SM_SSC   (SM_STAG + 256)      // 143616
#define SM_SPAR  (SM_SSC + 256)       // 143872
#define SM_SPS   (SM_SPAR + 256)      // 144128
#define SM_TOTAL (SM_SPS + 256)       // 144384

__global__ void __launch_bounds__(256, 1)
k_persist(const float* __restrict__ emis,
          const int* __restrict__ tags,
          const float* __restrict__ mask,
          const float* __restrict__ b_hh,
          const float* __restrict__ b_lin) {
    extern __shared__ char sm[];
    __nv_bfloat16* Hhi  = (__nv_bfloat16*)sm;
    __nv_bfloat16* Hlo  = Hhi + 64 * PITCH;
    __nv_bfloat16* HPhi = Hlo + 64 * PITCH;
    __nv_bfloat16* HPlo = HPhi + 64 * PITCH;
    float* cand = (float*)(sm + SM_CAND);   // [64 rows][32 cols]
    int*   stag = (int*)  (sm + SM_STAG);   // per-row tag (beam tag / path x-tag)
    float* sSc  = (float*)(sm + SM_SSC);    // [2 batches][32 slots]
    int*   sPar = (int*)  (sm + SM_SPAR);
    float* sPS  = (float*)(sm + SM_SPS);

    int tid = threadIdx.x;
    int bid = blockIdx.x;
    bool isPath = (bid >= 128);
    int bo = isPath ? (bid - 128) * 64 : 0;
    int w = tid >> 5, l = tid & 31;

    // ---- load initial state: f32 H -> bf16 hi/lo ----
    {
        const float* src = d_Hid + (isPath ? (NRQ + bo) : bid * 64) * HQ;
        for (int e = tid; e < 64 * 256; e += 256) {
            int r = e >> 8, c = e & 255;
            float v = src[r * 256 + c];
            __nv_bfloat16 hh = __float2bfloat16(v);
            Hhi[r * PITCH + c] = hh;
            Hlo[r * PITCH + c] = __float2bfloat16(v - __bfloat162float(hh));
        }
        if (tid < 64) {
            if (!isPath) { stag[tid] = d_Btags[bid * 64 + tid]; sSc[tid] = d_Sc[bid * 64 + tid]; }
            else sPS[tid] = d_PS[bo + tid];
        }
    }
    __syncthreads();

    const uint2* WB2  = reinterpret_cast<const uint2*>(d_WB);
    const uint2* WLB2 = reinterpret_cast<const uint2*>(d_WLB);
    u32 abase_hi = s2u(Hhi)  + ((l & 15) * PITCH + (l >> 4) * 8) * 2;
    u32 pbase_hi = s2u(HPhi) + ((l & 15) * PITCH + (l >> 4) * 8) * 2;

    for (int t = 1; t < LQ; t++) {
        if (isPath && tid < 64) stag[tid] = tags[(t - 1) * BQ + bo + tid];
        __syncthreads();

        // ======== gate GEMM: G[64][768] = Hsplit @ Wsplit (3-term bf16) ========
        for (int c0 = 0; c0 < 4; c0++) {
            int ntr = c0 * 8 + w;     // r ntile; z: +32; n: +64
            float acc[3][16];
            #pragma unroll
            for (int g = 0; g < 3; g++)
                #pragma unroll
                for (int i = 0; i < 16; i++) acc[g][i] = 0.f;

            #pragma unroll 2
            for (int kt = 0; kt < 16; kt++) {
                u32 ah[4][4], al[4][4];
                #pragma unroll
                for (int mt = 0; mt < 4; mt++) {
                    u32 off = (mt * 16 * PITCH + kt * 16) * 2;
                    ldmx4(ah[mt], abase_hi + off);
                    ldmx4(al[mt], abase_hi + SMB + off);   // Hlo is contiguous after Hhi
                }
                #pragma unroll
                for (int g = 0; g < 3; g++) {
                    int nt = ntr + g * 32;
                    uint2 bh = WB2[(nt * 16 + kt) * 32 + l];
                    uint2 bl = WB2[((96 + nt) * 16 + kt) * 32 + l];
                    #pragma unroll
                    for (int mt = 0; mt < 4; mt++) {
                        mma16816(&acc[g][mt * 4], ah[mt], bh);
                        mma16816(&acc[g][mt * 4], al[mt], bh);
                        mma16816(&acc[g][mt * 4], ah[mt], bl);
                    }
                }
            }
            // ---- gate epilogue: h' for this 64-col slice ----
            #pragma unroll
            for (int mt = 0; mt < 4; mt++) {
                #pragma unroll
                for (int reg = 0; reg < 4; reg++) {
                    int row = mt * 16 + (l >> 2) + ((reg >> 1) << 3);
                    int col = c0 * 64 + w * 8 + 2 * (l & 3) + (reg & 1);
                    int xt = stag[row];
                    const float* gix = d_XG + xt * GQ + col;
                    float gr = fsig(gix[0]      + acc[0][mt * 4 + reg]);
                    float gz = fsig(gix[HQ]     + acc[1][mt * 4 + reg]);
                    float gn = ftanh(gix[2 * HQ] + gr * (acc[2][mt * 4 + reg] + b_hh[2 * HQ + col]));
                    float hold = __bfloat162float(Hhi[row * PITCH + col]) +
                                 __bfloat162float(Hlo[row * PITCH + col]);
                    float hv = gn + gz * (hold - gn);
                    __nv_bfloat16 hh = __float2bfloat16(hv);
                    HPhi[row * PITCH + col] = hh;
                    HPlo[row * PITCH + col] = __float2bfloat16(hv - __bfloat162float(hh));
                }
            }
        }
        __syncthreads();   // HP complete

        // ======== TR GEMM: TR[64][32] = h'split @ WLsplit ========
        {
            int mt = w & 3, np = w >> 2;
            float tacc[2][4];
            #pragma unroll
            for (int j = 0; j < 2; j++)
                #pragma unroll
                for (int i = 0; i < 4; i++) tacc[j][i] = 0.f;

            #pragma unroll 2
            for (int kt = 0; kt < 16; kt++) {
                u32 ah[4], al[4];
                u32 off = (mt * 16 * PITCH + kt * 16) * 2;
                ldmx4(ah, pbase_hi + off);
                ldmx4(al, pbase_hi + SMB + off);   // HPlo contiguous after HPhi
                #pragma unroll
                for (int j = 0; j < 2; j++) {
                    int nt = np * 2 + j;
                    uint2 bh = WLB2[(nt * 16 + kt) * 32 + l];
                    uint2 bl = WLB2[((4 + nt) * 16 + kt) * 32 + l];
                    mma16816(tacc[j], ah, bh);
                    mma16816(tacc[j], al, bh);
                    mma16816(tacc[j], ah, bl);
                }
            }
            // ---- TR epilogue ----
            #pragma unroll
            for (int j = 0; j < 2; j++) {
                #pragma unroll
                for (int reg = 0; reg < 4; reg++) {
                    int row = mt * 16 + (l >> 2) + ((reg >> 1) << 3);
                    int col = (np * 2 + j) * 8 + 2 * (l & 3) + (reg & 1);
                    float ta = tacc[j][reg] + b_lin[col];
                    if (!isPath) {
                        int batch = 2 * bid + (row >> 5);
                        float em = emis[(t * BQ + batch) * TQ + col];
                        float m  = mask[t * BQ + batch];
                        float base = sSc[(row & 32) + stag[row]];  // quirk: gather by beam TAG id
                        cand[row * TQ + col] = base + (ta + em) * m;
                    } else {
                        int b = bo + row;
                        int cur = tags[t * BQ + b];
                        if (col == cur)   // em0 quirk: emissions[0] every step
                            sPS[row] += (ta + emis[b * TQ + cur]) * mask[t * BQ + b];
                    }
                }
            }
        }
        __syncthreads();

        // ======== top-32 select (2 warps, one per batch) ========
        if (!isPath && tid < 64) {
            int batch = tid >> 5, lane = tid & 31;
            float c[32];
            #pragma unroll
            for (int j = 0; j < 32; j++) c[j] = cand[(batch * 32 + j) * TQ + lane];
            for (int i = 0; i < KQ; i++) {
                float bv = -INFINITY; int bj = 0;
                #pragma unroll
                for (int j = 0; j < 32; j++)
                    if (c[j] > bv) { bv = c[j]; bj = j; }   // '>' keeps smallest flat idx
                int bi = bj * 32 + lane;
                #pragma unroll
                for (int off = 16; off; off >>= 1) {
                    float ov = __shfl_down_sync(0xffffffffu, bv, off);
                    int   oi = __shfl_down_sync(0xffffffffu, bi, off);
                    if (ov > bv || (ov == bv && oi < bi)) { bv = ov; bi = oi; }
                }
                bv = __shfl_sync(0xffffffffu, bv, 0);
                bi = __shfl_sync(0xffffffffu, bi, 0);
                if (lane == 0) {
                    sSc[batch * 32 + i]  = bv;
                    stag[batch * 32 + i] = bi & 31;
                    sPar[batch * 32 + i] = batch * 32 + (bi >> 5);
                }
                if ((bi & 31) == lane) c[bi >> 5] = -INFINITY;
            }
        }
        __syncthreads();

        // ======== gather HP -> H (row permutation for beams, copy for path) ========
        #pragma unroll
        for (int rr = 0; rr < 8; rr++) {
            int r = w * 8 + rr;
            int p = isPath ? r : sPar[r];
            const u32* s1 = (const u32*)(HPhi + p * PITCH);
            const u32* s2 = (const u32*)(HPlo + p * PITCH);
            u32* dH = (u32*)(Hhi + r * PITCH);
            u32* dL = (u32*)(Hlo + r * PITCH);
            #pragma unroll
            for (int i = l; i < 128; i += 32) { dH[i] = s1[i]; dL[i] = s2[i]; }
        }
        __syncthreads();
    }

    // ---- writeback ----
    if (tid < 64) {
        if (!isPath) d_Sc[bid * 64 + tid] = sSc[tid];
        else         d_PS[bo + tid] = sPS[tid];
    }
}

// ---------------- finalize ----------------
__global__ void k_final(float* __restrict__ out) {
    __shared__ float red[BQ];
    int b = threadIdx.x;
    float m = -INFINITY;
    for (int i = 0; i < KQ; i++) m = fmaxf(m, d_Sc[b * KQ + i]);
    float s = 0.f;
    for (int i = 0; i < KQ; i++) s += expf(d_Sc[b * KQ + i] - m);
    float lse = m + logf(s);
    red[b] = d_PS[b] - lse;
    __syncthreads();
    for (int off = 128; off; off >>= 1) {
        if (b < off) red[b] += red[b + off];
        __syncthreads();
    }
    if (b == 0) out[0] = red[0];
}

// ---------------- launch ----------------
extern "C" void kernel_launch(void* const* d_in, const int* in_sizes, int n_in,
                              void* d_out, int out_size) {
    const float* emissions = (const float*)d_in[0];
    const int*   tags      = (const int*)  d_in[1];
    const float* mask      = (const float*)d_in[2];
    const float* embedding = (const float*)d_in[3];
    const float* W_ih      = (const float*)d_in[4];
    const float* W_hh      = (const float*)d_in[5];
    const float* b_ih      = (const float*)d_in[6];
    const float* b_hh      = (const float*)d_in[7];
    const float* W_lin     = (const float*)d_in[8];
    const float* b_lin     = (const float*)d_in[9];
    float* out = (float*)d_out;

    cudaFuncSetAttribute(k_persist, cudaFuncAttributeMaxDynamicSharedMemorySize, SM_TOTAL);

    k_prep_xg<<<(33 * GQ * 32 + 255) / 256, 256>>>(W_ih, embedding, b_ih, b_hh);
    k_prep_wb<<<(2 * 96 * 16 * 64 + 2 * 4 * 16 * 64 + 255) / 256, 256>>>(W_hh, W_lin);
    k_prep_h1<<<1, 256>>>(b_hh, W_lin, b_lin);
    k_prep_init<<<BQ / 8, 256>>>(emissions, tags, mask);

    k_persist<<<GRIDP, 256, SM_TOTAL>>>(emissions, tags, mask, b_hh, b_lin);

    k_final<<<1, 256>>>(out);
}

// round 13
// speedup vs baseline: 1.9265x; 1.0003x over previous
#include <cuda_runtime.h>
#include <cuda_bf16.h>
#include <math.h>

#define LQ 64
#define BQ 256
#define TQ 32
#define EQ 256
#define HQ 256
#define GQ 768
#define KQ 32
#define NRQ 8192
#define PITCH 264          // bf16 elems per smem row (528B, conflict-free ldmatrix)
#define GRIDP 132          // 128 beam CTAs (2 batches each) + 4 path CTAs (64 chains each)

typedef unsigned int u32;

// ---------------- device scratch ----------------
__device__ float d_XG[33 * GQ];          // x-gates per tag; b_ih always; +b_hh for r,z parts
__device__ float d_h1[HQ];
__device__ float d_trans0[TQ];
__device__ float d_Hid[(NRQ + BQ) * HQ];
__device__ float d_Sc[BQ * KQ];
__device__ int   d_Btags[BQ * KQ];
__device__ float d_PS[BQ];
__device__ u32   d_WB[2 * 96 * 16 * 64];   // gate B fragments: [hi/lo][ntile 96][ktile 16][lane*2+reg]
__device__ u32   d_WLB[2 * 4 * 16 * 64];   // TR  B fragments: [hi/lo][ntile 4][ktile 16][lane*2+reg]

// ---------------- helpers ----------------
__device__ __forceinline__ float fsig(float x)  { return 1.0f / (1.0f + __expf(-x)); }
__device__ __forceinline__ float ftanh(float x) { return 2.0f / (1.0f + __expf(-2.0f * x)) - 1.0f; }

__device__ __forceinline__ u32 s2u(const void* p) { return (u32)__cvta_generic_to_shared(p); }

__device__ __forceinline__ void ldmx4(u32* r, u32 addr) {
    asm volatile("ldmatrix.sync.aligned.m8n8.x4.shared.b16 {%0,%1,%2,%3}, [%4];"
                 : "=r"(r[0]), "=r"(r[1]), "=r"(r[2]), "=r"(r[3]) : "r"(addr));
}
__device__ __forceinline__ void mma16816(float* d, const u32* a, uint2 b) {
    asm volatile("mma.sync.aligned.m16n8k16.row.col.f32.bf16.bf16.f32 "
                 "{%0,%1,%2,%3}, {%4,%5,%6,%7}, {%8,%9}, {%0,%1,%2,%3};"
                 : "+f"(d[0]), "+f"(d[1]), "+f"(d[2]), "+f"(d[3])
                 : "r"(a[0]), "r"(a[1]), "r"(a[2]), "r"(a[3]), "r"(b.x), "r"(b.y));
}
__device__ __forceinline__ u32 packbf(float a, float b) {
    __nv_bfloat162 p;
    p.x = __float2bfloat16(a);
    p.y = __float2bfloat16(b);
    return *reinterpret_cast<u32*>(&p);
}

// ---------------- prep: XG[33][768] = W_ih @ emb[t] + b_ih (+ b_hh for r,z cols) ----------------
__global__ void k_prep_xg(const float* __restrict__ W_ih,
                          const float* __restrict__ emb,
                          const float* __restrict__ b_ih,
                          const float* __restrict__ b_hh) {
    int o = (blockIdx.x * blockDim.x + threadIdx.x) >> 5;
    int lane = threadIdx.x & 31;
    if (o >= 33 * GQ) return;
    int t = o / GQ, c = o % GQ;
    const float* wr = W_ih + c * EQ;
    const float* er = emb + t * EQ;
    float acc = 0.f;
    for (int k = lane; k < EQ; k += 32) acc += wr[k] * er[k];
    #pragma unroll
    for (int off = 16; off; off >>= 1) acc += __shfl_down_sync(0xffffffffu, acc, off);
    if (lane == 0) {
        float v = acc + b_ih[c];
        if (c < 2 * HQ) v += b_hh[c];   // fold b_hh into r and z parts
        d_XG[o] = v;
    }
}

// ---------------- prep: B fragment tables (bf16 hi/lo, exact mma lane order) ----------------
__global__ void k_prep_wb(const float* __restrict__ W_hh,
                          const float* __restrict__ W_lin) {
    int idx = blockIdx.x * blockDim.x + threadIdx.x;
    const int NG = 2 * 96 * 16 * 64;
    if (idx < NG) {
        int e = idx;
        int reg = e & 1;  e >>= 1;
        int lane = e & 31; e >>= 5;
        int kt = e & 15;  e >>= 4;
        int nt = e % 96;
        int wt = e / 96;
        int k0 = kt * 16 + 2 * (lane & 3) + reg * 8;
        int n  = nt * 8 + (lane >> 2);
        float w0 = W_hh[n * HQ + k0], w1 = W_hh[n * HQ + k0 + 1];
        if (wt == 0) d_WB[idx] = packbf(w0, w1);
        else {
            float h0 = __bfloat162float(__float2bfloat16(w0));
            float h1 = __bfloat162float(__float2bfloat16(w1));
            d_WB[idx] = packbf(w0 - h0, w1 - h1);
        }
    } else if (idx < NG + 2 * 4 * 16 * 64) {
        int e = idx - NG;
        int i2 = e;
        int reg = e & 1;  e >>= 1;
        int lane = e & 31; e >>= 5;
        int kt = e & 15;  e >>= 4;
        int nt = e % 4;
        int wt = e / 4;
        int k0 = kt * 16 + 2 * (lane & 3) + reg * 8;
        int n  = nt * 8 + (lane >> 2);
        float w0 = W_lin[n * HQ + k0], w1 = W_lin[n * HQ + k0 + 1];
        if (wt == 0) d_WLB[i2] = packbf(w0, w1);
        else {
            float h0 = __bfloat162float(__float2bfloat16(w0));
            float h1 = __bfloat162float(__float2bfloat16(w1));
            d_WLB[i2] = packbf(w0 - h0, w1 - h1);
        }
    }
}

// ---------------- prep: h1 = gru(emb[T], 0), trans0 = lin(h1) ----------------
__global__ void k_prep_h1(const float* __restrict__ b_hh,
                          const float* __restrict__ W_lin,
                          const float* __restrict__ b_lin) {
    __shared__ float h1s[HQ];
    int j = threadIdx.x;
    float r = fsig(d_XG[32 * GQ + j]);                 // b_hh folded
    float z = fsig(d_XG[32 * GQ + HQ + j]);
    float n = ftanh(d_XG[32 * GQ + 2 * HQ + j] + r * b_hh[2 * HQ + j]);
    float h = (1.f - z) * n;   // h0 == 0
    h1s[j] = h;
    d_h1[j] = h;
    __syncthreads();
    if (j < TQ) {
        float acc = b_lin[j];
        const float* wr = W_lin + j * HQ;
        for (int k = 0; k < HQ; k++) acc += wr[k] * h1s[k];
        d_trans0[j] = acc;
    }
}

// ---------------- prep: initial scores / beams / hidden / path score ----------------
__global__ void k_prep_init(const float* __restrict__ emis,
                            const int* __restrict__ tags,
                            const float* __restrict__ mask) {
    int w = threadIdx.x >> 5, lane = threadIdx.x & 31;
    int b = blockIdx.x * 8 + w;
    float m0 = mask[b];
    float v = (d_trans0[lane] + emis[b * TQ + lane]) * m0;
    int rank = 0;
    for (int j = 0; j < 32; j++) {
        float vj = __shfl_sync(0xffffffffu, v, j);
        rank += (vj > v) || (vj == v && j < lane);
    }
    d_Sc[b * KQ + rank]    = v;
    d_Btags[b * KQ + rank] = lane;
    if (lane == 0) {
        int t0 = tags[b];
        d_PS[b] = (d_trans0[t0] + emis[b * TQ + t0]) * m0;
    }
    for (int r = 0; r < KQ; r++) {
        float* dst = d_Hid + (b * KQ + r) * HQ;
        for (int c = lane; c < HQ; c += 32) dst[c] = d_h1[c];
    }
    float* dst = d_Hid + (NRQ + b) * HQ;
    for (int c = lane; c < HQ; c += 32) dst[c] = d_h1[c];
}

// ================= persistent fused stepper (tensor-core) =================
// smem: Hhi|Hlo|HPhi|HPlo (bf16, pitch 264) + cand + small state
#define SMB   (64 * PITCH * 2)        // 33792 bytes per bf16 buffer
#define SM_CAND  (4 * SMB)            // 135168
#define SM_STAG  (SM_CAND + 8192)     // 143360
#define SM_SSC   (SM_STAG + 256)      // 143616
#define SM_SPAR  (SM_SSC + 256)       // 143872
#define SM_SPS   (SM_SPAR + 256)      // 144128
#define SM_TOTAL (SM_SPS + 256)       // 144384

__global__ void __launch_bounds__(256, 1)
k_persist(const float* __restrict__ emis,
          const int* __restrict__ tags,
          const float* __restrict__ mask,
          const float* __restrict__ b_hh,
          const float* __restrict__ b_lin) {
    extern __shared__ char sm[];
    __nv_bfloat16* Hhi  = (__nv_bfloat16*)sm;
    __nv_bfloat16* Hlo  = Hhi + 64 * PITCH;
    __nv_bfloat16* HPhi = Hlo + 64 * PITCH;
    __nv_bfloat16* HPlo = HPhi + 64 * PITCH;
    float* cand = (float*)(sm + SM_CAND);   // [64 rows][32 cols]
    int*   stag = (int*)  (sm + SM_STAG);   // per-row tag (beam tag / path x-tag)
    float* sSc  = (float*)(sm + SM_SSC);    // [2 batches][32 slots]
    int*   sPar = (int*)  (sm + SM_SPAR);
    float* sPS  = (float*)(sm + SM_SPS);

    int tid = threadIdx.x;
    int bid = blockIdx.x;
    bool isPath = (bid >= 128);
    int bo = isPath ? (bid - 128) * 64 : 0;
    int w = tid >> 5, l = tid & 31;

    // ---- load initial state: f32 H -> bf16 hi/lo ----
    {
        const float* src = d_Hid + (isPath ? (NRQ + bo) : bid * 64) * HQ;
        for (int e = tid; e < 64 * 256; e += 256) {
            int r = e >> 8, c = e & 255;
            float v = src[r * 256 + c];
            __nv_bfloat16 hh = __float2bfloat16(v);
            Hhi[r * PITCH + c] = hh;
            Hlo[r * PITCH + c] = __float2bfloat16(v - __bfloat162float(hh));
        }
        if (tid < 64) {
            if (!isPath) { stag[tid] = d_Btags[bid * 64 + tid]; sSc[tid] = d_Sc[bid * 64 + tid]; }
            else sPS[tid] = d_PS[bo + tid];
        }
    }
    __syncthreads();

    const uint2* WB2  = reinterpret_cast<const uint2*>(d_WB);
    const uint2* WLB2 = reinterpret_cast<const uint2*>(d_WLB);
    u32 abase_hi = s2u(Hhi)  + ((l & 15) * PITCH + (l >> 4) * 8) * 2;
    u32 pbase_hi = s2u(HPhi) + ((l & 15) * PITCH + (l >> 4) * 8) * 2;

    for (int t = 1; t < LQ; t++) {
        if (isPath && tid < 64) stag[tid] = tags[(t - 1) * BQ + bo + tid];
        __syncthreads();

        // ======== gate GEMM: G[64][768] = Hsplit @ Wsplit (3-term bf16) ========
        for (int c0 = 0; c0 < 4; c0++) {
            int ntr = c0 * 8 + w;     // r ntile; z: +32; n: +64
            float acc[3][16];
            #pragma unroll
            for (int g = 0; g < 3; g++)
                #pragma unroll
                for (int i = 0; i < 16; i++) acc[g][i] = 0.f;

            #pragma unroll 2
            for (int kt = 0; kt < 16; kt++) {
                u32 ah[4][4], al[4][4];
                #pragma unroll
                for (int mt = 0; mt < 4; mt++) {
                    u32 off = (mt * 16 * PITCH + kt * 16) * 2;
                    ldmx4(ah[mt], abase_hi + off);
                    ldmx4(al[mt], abase_hi + SMB + off);   // Hlo is contiguous after Hhi
                }
                #pragma unroll
                for (int g = 0; g < 3; g++) {
                    int nt = ntr + g * 32;
                    uint2 bh = WB2[(nt * 16 + kt) * 32 + l];
                    uint2 bl = WB2[((96 + nt) * 16 + kt) * 32 + l];
                    #pragma unroll
                    for (int mt = 0; mt < 4; mt++) {
                        mma16816(&acc[g][mt * 4], ah[mt], bh);
                        mma16816(&acc[g][mt * 4], al[mt], bh);
                        mma16816(&acc[g][mt * 4], ah[mt], bl);
                    }
                }
            }
            // ---- gate epilogue: h' for this 64-col slice ----
            #pragma unroll
            for (int mt = 0; mt < 4; mt++) {
                #pragma unroll
                for (int reg = 0; reg < 4; reg++) {
                    int row = mt * 16 + (l >> 2) + ((reg >> 1) << 3);
                    int col = c0 * 64 + w * 8 + 2 * (l & 3) + (reg & 1);
                    int xt = stag[row];
                    const float* gix = d_XG + xt * GQ + col;
                    float gr = fsig(gix[0]      + acc[0][mt * 4 + reg]);
                    float gz = fsig(gix[HQ]     + acc[1][mt * 4 + reg]);
                    float gn = ftanh(gix[2 * HQ] + gr * (acc[2][mt * 4 + reg] + b_hh[2 * HQ + col]));
                    float hold = __bfloat162float(Hhi[row * PITCH + col]) +
                                 __bfloat162float(Hlo[row * PITCH + col]);
                    float hv = gn + gz * (hold - gn);
                    __nv_bfloat16 hh = __float2bfloat16(hv);
                    HPhi[row * PITCH + col] = hh;
                    HPlo[row * PITCH + col] = __float2bfloat16(hv - __bfloat162float(hh));
                }
            }
        }
        __syncthreads();   // HP complete

        // ======== TR GEMM: TR[64][32] = h'split @ WLsplit ========
        {
            int mt = w & 3, np = w >> 2;
            float tacc[2][4];
            #pragma unroll
            for (int j = 0; j < 2; j++)
                #pragma unroll
                for (int i = 0; i < 4; i++) tacc[j][i] = 0.f;

            #pragma unroll 2
            for (int kt = 0; kt < 16; kt++) {
                u32 ah[4], al[4];
                u32 off = (mt * 16 * PITCH + kt * 16) * 2;
                ldmx4(ah, pbase_hi + off);
                ldmx4(al, pbase_hi + SMB + off);   // HPlo contiguous after HPhi
                #pragma unroll
                for (int j = 0; j < 2; j++) {
                    int nt = np * 2 + j;
                    uint2 bh = WLB2[(nt * 16 + kt) * 32 + l];
                    uint2 bl = WLB2[((4 + nt) * 16 + kt) * 32 + l];
                    mma16816(tacc[j], ah, bh);
                    mma16816(tacc[j], al, bh);
                    mma16816(tacc[j], ah, bl);
                }
            }
            // ---- TR epilogue ----
            #pragma unroll
            for (int j = 0; j < 2; j++) {
                #pragma unroll
                for (int reg = 0; reg < 4; reg++) {
                    int row = mt * 16 + (l >> 2) + ((reg >> 1) << 3);
                    int col = (np * 2 + j) * 8 + 2 * (l & 3) + (reg & 1);
                    float ta = tacc[j][reg] + b_lin[col];
                    if (!isPath) {
                        int batch = 2 * bid + (row >> 5);
                        float em = emis[(t * BQ + batch) * TQ + col];
                        float m  = mask[t * BQ + batch];
                        float base = sSc[(row & 32) + stag[row]];  // quirk: gather by beam TAG id
                        cand[row * TQ + col] = base + (ta + em) * m;
                    } else {
                        int b = bo + row;
                        int cur = tags[t * BQ + b];
                        if (col == cur)   // em0 quirk: emissions[0] every step
                            sPS[row] += (ta + emis[b * TQ + cur]) * mask[t * BQ + b];
                    }
                }
            }
        }
        __syncthreads();

        // ======== top-32 select (2 warps, one per batch) ========
        if (!isPath && tid < 64) {
            int batch = tid >> 5, lane = tid & 31;
            float c[32];
            #pragma unroll
            for (int j = 0; j < 32; j++) c[j] = cand[(batch * 32 + j) * TQ + lane];
            for (int i = 0; i < KQ; i++) {
                float bv = -INFINITY; int bj = 0;
                #pragma unroll
                for (int j = 0; j < 32; j++)
                    if (c[j] > bv) { bv = c[j]; bj = j; }   // '>' keeps smallest flat idx
                int bi = bj * 32 + lane;
                #pragma unroll
                for (int off = 16; off; off >>= 1) {
                    float ov = __shfl_down_sync(0xffffffffu, bv, off);
                    int   oi = __shfl_down_sync(0xffffffffu, bi, off);
                    if (ov > bv || (ov == bv && oi < bi)) { bv = ov; bi = oi; }
                }
                bv = __shfl_sync(0xffffffffu, bv, 0);
                bi = __shfl_sync(0xffffffffu, bi, 0);
                if (lane == 0) {
                    sSc[batch * 32 + i]  = bv;
                    stag[batch * 32 + i] = bi & 31;
                    sPar[batch * 32 + i] = batch * 32 + (bi >> 5);
                }
                if ((bi & 31) == lane) c[bi >> 5] = -INFINITY;
            }
        }
        __syncthreads();

        // ======== gather HP -> H (row permutation for beams, copy for path) ========
        #pragma unroll
        for (int rr = 0; rr < 8; rr++) {
            int r = w * 8 + rr;
            int p = isPath ? r : sPar[r];
            const u32* s1 = (const u32*)(HPhi + p * PITCH);
            const u32* s2 = (const u32*)(HPlo + p * PITCH);
            u32* dH = (u32*)(Hhi + r * PITCH);
            u32* dL = (u32*)(Hlo + r * PITCH);
            #pragma unroll
            for (int i = l; i < 128; i += 32) { dH[i] = s1[i]; dL[i] = s2[i]; }
        }
        __syncthreads();
    }

    // ---- writeback ----
    if (tid < 64) {
        if (!isPath) d_Sc[bid * 64 + tid] = sSc[tid];
        else         d_PS[bo + tid] = sPS[tid];
    }
}

// ---------------- finalize ----------------
__global__ void k_final(float* __restrict__ out) {
    __shared__ float red[BQ];
    int b = threadIdx.x;
    float m = -INFINITY;
    for (int i = 0; i < KQ; i++) m = fmaxf(m, d_Sc[b * KQ + i]);
    float s = 0.f;
    for (int i = 0; i < KQ; i++) s += expf(d_Sc[b * KQ + i] - m);
    float lse = m + logf(s);
    red[b] = d_PS[b] - lse;
    __syncthreads();
    for (int off = 128; off; off >>= 1) {
        if (b < off) red[b] += red[b + off];
        __syncthreads();
    }
    if (b == 0) out[0] = red[0];
}

// ---------------- launch ----------------
extern "C" void kernel_launch(void* const* d_in, const int* in_sizes, int n_in,
                              void* d_out, int out_size) {
    const float* emissions = (const float*)d_in[0];
    const int*   tags      = (const int*)  d_in[1];
    const float* mask      = (const float*)d_in[2];
    const float* embedding = (const float*)d_in[3];
    const float* W_ih      = (const float*)d_in[4];
    const float* W_hh      = (const float*)d_in[5];
    const float* b_ih      = (const float*)d_in[6];
    const float* b_hh      = (const float*)d_in[7];
    const float* W_lin     = (const float*)d_in[8];
    const float* b_lin     = (const float*)d_in[9];
    float* out = (float*)d_out;

    cudaFuncSetAttribute(k_persist, cudaFuncAttributeMaxDynamicSharedMemorySize, SM_TOTAL);

    k_prep_xg<<<(33 * GQ * 32 + 255) / 256, 256>>>(W_ih, embedding, b_ih, b_hh);
    k_prep_wb<<<(2 * 96 * 16 * 64 + 2 * 4 * 16 * 64 + 255) / 256, 256>>>(W_hh, W_lin);
    k_prep_h1<<<1, 256>>>(b_hh, W_lin, b_lin);
    k_prep_init<<<BQ / 8, 256>>>(emissions, tags, mask);

    k_persist<<<GRIDP, 256, SM_TOTAL>>>(emissions, tags, mask, b_hh, b_lin);

    k_final<<<1, 256>>>(out);
}